// round 12
// baseline (speedup 1.0000x reference)
#include <cuda_runtime.h>
#include <cuda_bf16.h>

#define N_NODES 100000
#define N_EDGES 1600000

// ---------------- scratch: __device__ globals --------------------------------
__device__ __align__(16) float g_h[N_NODES * 64];     // GEMM output / gather src
__device__ __align__(16) float g_agg[N_NODES * 64];   // aggregation output
__device__ float g_dinv[N_NODES];
__device__ int   g_deg[N_NODES];
__device__ int   g_cur[N_NODES];
__device__ int   g_off[N_NODES + 1];
__device__ __align__(8) int2 g_epack[N_EDGES];        // {src, norm-as-int} per CSR slot
__device__ int   g_is64;

// ---------------- zero + dtype detect ----------------------------------------
// int64 edge values < 2^31 => every odd 32-bit word is 0; int32 uniform in
// [0,100000) makes 256 consecutive odd words all-zero essentially impossible.
__global__ void k_zero(const int* __restrict__ ei) {
    int i = blockIdx.x * blockDim.x + threadIdx.x;
    if (i < N_NODES) { g_deg[i] = 0; g_cur[i] = 0; }
    if (blockIdx.x == 0) {
        __shared__ int nonzero;
        if (threadIdx.x == 0) nonzero = 0;
        __syncthreads();
        if (ei[2 * threadIdx.x + 1] != 0) atomicAdd(&nonzero, 1);
        __syncthreads();
        if (threadIdx.x == 0) g_is64 = (nonzero == 0) ? 1 : 0;
    }
}

__device__ __forceinline__ void decode_edge(const int* __restrict__ ei, int e,
                                            int& s, int& d) {
    if (g_is64) { s = ei[2 * e]; d = ei[2 * (N_EDGES + e)]; }
    else        { s = ei[e];     d = ei[N_EDGES + e]; }
    if ((unsigned)s >= N_NODES) s = 0;
    if ((unsigned)d >= N_NODES) d = 0;
}

// ---------------- pass 1: degree count ----------------------------------------
__global__ void k_pre(const int* __restrict__ ei) {
    int e = blockIdx.x * blockDim.x + threadIdx.x;
    if (e >= N_EDGES) return;
    int s, d;
    decode_edge(ei, e, s, d);
    atomicAdd(&g_deg[d], 1);
}

// ---------------- prefix scan of degrees -> offsets, plus dinv ----------------
__global__ void k_scan() {
    __shared__ int partial[1024];
    const int tid = threadIdx.x;
    const int chunk = (N_NODES + 1023) / 1024;  // 98
    const int start = tid * chunk;
    const int end = min(start + chunk, N_NODES);

    int s = 0;
    for (int i = start; i < end; i++) s += g_deg[i];
    partial[tid] = s;
    __syncthreads();

    for (int off = 1; off < 1024; off <<= 1) {
        int v = 0;
        if (tid >= off) v = partial[tid - off];
        __syncthreads();
        partial[tid] += v;
        __syncthreads();
    }

    int run = (tid > 0) ? partial[tid - 1] : 0;  // exclusive base
    for (int i = start; i < end; i++) {
        g_off[i] = run;
        int dg = g_deg[i];
        run += dg;
        g_dinv[i] = rsqrtf((float)(dg + 1));  // +1: self-loop
    }
    if (start < N_NODES && end == N_NODES) g_off[N_NODES] = run;
}

// ---------------- pass 2: re-decode, compute norm, place into CSR -------------
__global__ void k_place(const int* __restrict__ ei) {
    int e = blockIdx.x * blockDim.x + threadIdx.x;
    if (e >= N_EDGES) return;
    int s, d;
    decode_edge(ei, e, s, d);
    float nz = g_dinv[s] * g_dinv[d];
    int pos = g_off[d] + atomicAdd(&g_cur[d], 1);
    g_epack[pos] = make_int2(s, __float_as_int(nz));
}

// ---------------- GEMM: [32 rows] x [64 -> OUT] (R7 config) -------------------
template <int OUT, bool FROM_X>
__global__ void k_gemm(const float* __restrict__ x, const float* __restrict__ W) {
    constexpr int QUADS = OUT / 4;
    constexpr int RPT = (32 * QUADS) / 256;  // 2 for OUT=64, 1 for OUT=32
    __shared__ float Ws[64 * OUT];
    __shared__ float xs[32][65];  // pad kills stride-64 bank conflicts

    const int tid = threadIdx.x;
    const int row0 = blockIdx.x * 32;  // N_NODES % 32 == 0

    for (int i = tid; i < 64 * OUT; i += 256) Ws[i] = W[i];

    for (int i = tid; i < 32 * 16; i += 256) {
        int r = i >> 4, c4 = i & 15;
        float4 v;
        if (FROM_X) {
            v = *(const float4*)&x[(size_t)(row0 + r) * 64 + c4 * 4];
        } else {
            v = *(const float4*)&g_agg[(size_t)(row0 + r) * 64 + c4 * 4];
            v.x = fmaxf(v.x, 0.f); v.y = fmaxf(v.y, 0.f);
            v.z = fmaxf(v.z, 0.f); v.w = fmaxf(v.w, 0.f);
        }
        xs[r][c4 * 4 + 0] = v.x; xs[r][c4 * 4 + 1] = v.y;
        xs[r][c4 * 4 + 2] = v.z; xs[r][c4 * 4 + 3] = v.w;
    }
    __syncthreads();

    const int colq = tid % QUADS;
    const int rg = tid / QUADS;

    float acc[RPT][4];
#pragma unroll
    for (int r = 0; r < RPT; r++) { acc[r][0] = acc[r][1] = acc[r][2] = acc[r][3] = 0.f; }

#pragma unroll
    for (int k = 0; k < 64; k++) {
        float4 w = *(const float4*)&Ws[k * OUT + colq * 4];
#pragma unroll
        for (int r = 0; r < RPT; r++) {
            float xv = xs[rg * RPT + r][k];
            acc[r][0] = fmaf(xv, w.x, acc[r][0]);
            acc[r][1] = fmaf(xv, w.y, acc[r][1]);
            acc[r][2] = fmaf(xv, w.z, acc[r][2]);
            acc[r][3] = fmaf(xv, w.w, acc[r][3]);
        }
    }

#pragma unroll
    for (int r = 0; r < RPT; r++) {
        int row = row0 + rg * RPT + r;
        *(float4*)&g_h[(size_t)row * OUT + colq * 4] =
            make_float4(acc[r][0], acc[r][1], acc[r][2], acc[r][3]);
    }
}

// ---------------- CSR aggregation: full warp per node, float2 columns ---------
// out[node] = dinv^2*h[node] + b + sum_e norm_e * h[src_e]
// OUT=64: lane owns float2 (cols 2L,2L+1) -> one LDG.64 per edge, fully coalesced.
// OUT=32: lane owns 1 float.
template <int OUT, bool TO_OUT>
__global__ void k_agg(const float* __restrict__ b, float* __restrict__ out) {
    const int warp = (blockIdx.x * blockDim.x + threadIdx.x) >> 5;
    const int lane = threadIdx.x & 31;
    if (warp >= N_NODES) return;
    const int node = warp;

    const int beg = g_off[node];
    const int end = g_off[node + 1];

    if (OUT == 64) {
        const float2* h2 = (const float2*)g_h;
        float2 acc;
        {
            float di = g_dinv[node];
            float sc = di * di;
            float2 hv = h2[(size_t)node * 32 + lane];
            float2 bq = ((const float2*)b)[lane];
            acc.x = fmaf(sc, hv.x, bq.x);
            acc.y = fmaf(sc, hv.y, bq.y);
        }
        int p = beg;
        for (; p + 2 <= end; p += 2) {
            int2 e0 = g_epack[p];
            int2 e1 = g_epack[p + 1];
            float n0 = __int_as_float(e0.y);
            float n1 = __int_as_float(e1.y);
            float2 h0 = h2[(size_t)e0.x * 32 + lane];
            float2 h1 = h2[(size_t)e1.x * 32 + lane];
            acc.x = fmaf(n0, h0.x, acc.x);
            acc.y = fmaf(n0, h0.y, acc.y);
            acc.x = fmaf(n1, h1.x, acc.x);
            acc.y = fmaf(n1, h1.y, acc.y);
        }
        if (p < end) {
            int2 e0 = g_epack[p];
            float n0 = __int_as_float(e0.y);
            float2 h0 = h2[(size_t)e0.x * 32 + lane];
            acc.x = fmaf(n0, h0.x, acc.x);
            acc.y = fmaf(n0, h0.y, acc.y);
        }
        if (TO_OUT) ((float2*)out)[(size_t)node * 32 + lane] = acc;
        else        ((float2*)g_agg)[(size_t)node * 32 + lane] = acc;
    } else {
        float acc;
        {
            float di = g_dinv[node];
            float sc = di * di;
            acc = fmaf(sc, g_h[(size_t)node * 32 + lane], b[lane]);
        }
        int p = beg;
        for (; p + 2 <= end; p += 2) {
            int2 e0 = g_epack[p];
            int2 e1 = g_epack[p + 1];
            acc = fmaf(__int_as_float(e0.y), g_h[(size_t)e0.x * 32 + lane], acc);
            acc = fmaf(__int_as_float(e1.y), g_h[(size_t)e1.x * 32 + lane], acc);
        }
        if (p < end) {
            int2 e0 = g_epack[p];
            acc = fmaf(__int_as_float(e0.y), g_h[(size_t)e0.x * 32 + lane], acc);
        }
        if (TO_OUT) out[(size_t)node * 32 + lane] = acc;
        else        g_agg[(size_t)node * 32 + lane] = acc;
    }
}

// ---------------- launch: kernel launches ONLY --------------------------------
extern "C" void kernel_launch(void* const* d_in, const int* in_sizes, int n_in,
                              void* d_out, int out_size) {
    const float* x  = (const float*)d_in[0];
    const int* ei   = (const int*)d_in[1];   // int32 (JAX x64 off); int64 auto-detected
    const float* W1 = (const float*)d_in[2];
    const float* b1 = (const float*)d_in[3];
    const float* W2 = (const float*)d_in[4];
    const float* b2 = (const float*)d_in[5];
    const float* W3 = (const float*)d_in[6];
    const float* b3 = (const float*)d_in[7];
    float* out      = (float*)d_out;

    const int T = 256;
    const int gN = (N_NODES + T - 1) / T;
    const int gE = (N_EDGES + T - 1) / T;
    const int gW = (N_NODES * 32 + T - 1) / T;  // one warp per node

    // CSR build
    k_zero<<<gN, T>>>(ei);
    k_pre<<<gE, T>>>(ei);
    k_scan<<<1, 1024>>>();
    k_place<<<gE, T>>>(ei);

    // Layer 1
    k_gemm<64, true><<<N_NODES / 32, T>>>(x, W1);
    k_agg<64, false><<<gW, T>>>(b1, nullptr);

    // Layer 2
    k_gemm<64, false><<<N_NODES / 32, T>>>(nullptr, W2);
    k_agg<64, false><<<gW, T>>>(b2, nullptr);

    // Layer 3 (OUT=32) -> harness output
    k_gemm<32, false><<<N_NODES / 32, T>>>(nullptr, W3);
    k_agg<32, true><<<gW, T>>>(b3, out);
}

// round 15
// speedup vs baseline: 1.0061x; 1.0061x over previous
#include <cuda_runtime.h>
#include <cuda_fp16.h>

#define N_NODES 100000
#define N_EDGES 1600000

// ---------------- scratch: __device__ globals --------------------------------
__device__ __align__(16) __half g_hh[N_NODES * 64];   // GEMM output in fp16 (gather src)
__device__ __align__(16) float g_agg[N_NODES * 64];   // aggregation output (fp32)
__device__ float g_dinv[N_NODES];
__device__ int   g_deg[N_NODES];
__device__ int   g_cur[N_NODES];
__device__ int   g_off[N_NODES + 1];
__device__ int   g_src[N_EDGES];
__device__ int   g_dst[N_EDGES];
__device__ int   g_csrc[N_EDGES];
__device__ float g_cnorm[N_EDGES];
__device__ int   g_is64;

// ---------------- zero + dtype detect ----------------------------------------
// int64 edge values < 2^31 => every odd 32-bit word is 0; int32 uniform in
// [0,100000) makes 256 consecutive odd words all-zero essentially impossible.
__global__ void k_zero(const int* __restrict__ ei) {
    int i = blockIdx.x * blockDim.x + threadIdx.x;
    if (i < N_NODES) { g_deg[i] = 0; g_cur[i] = 0; }
    if (blockIdx.x == 0) {
        __shared__ int nonzero;
        if (threadIdx.x == 0) nonzero = 0;
        __syncthreads();
        if (ei[2 * threadIdx.x + 1] != 0) atomicAdd(&nonzero, 1);
        __syncthreads();
        if (threadIdx.x == 0) g_is64 = (nonzero == 0) ? 1 : 0;
    }
}

// ---------------- pass 1: decode + store COO + degree count ------------------
__global__ void k_pre(const int* __restrict__ ei) {
    int e = blockIdx.x * blockDim.x + threadIdx.x;
    if (e >= N_EDGES) return;
    int s, d;
    if (g_is64) { s = ei[2 * e]; d = ei[2 * (N_EDGES + e)]; }
    else        { s = ei[e];     d = ei[N_EDGES + e]; }
    if ((unsigned)s >= N_NODES) s = 0;
    if ((unsigned)d >= N_NODES) d = 0;
    g_src[e] = s;
    g_dst[e] = d;
    atomicAdd(&g_deg[d], 1);
}

// ---------------- prefix scan of degrees -> offsets, plus dinv ---------------
__global__ void k_scan() {
    __shared__ int partial[1024];
    const int tid = threadIdx.x;
    const int chunk = (N_NODES + 1023) / 1024;  // 98
    const int start = tid * chunk;
    const int end = min(start + chunk, N_NODES);

    int s = 0;
    for (int i = start; i < end; i++) s += g_deg[i];
    partial[tid] = s;
    __syncthreads();

    for (int off = 1; off < 1024; off <<= 1) {
        int v = 0;
        if (tid >= off) v = partial[tid - off];
        __syncthreads();
        partial[tid] += v;
        __syncthreads();
    }

    int run = (tid > 0) ? partial[tid - 1] : 0;  // exclusive base
    for (int i = start; i < end; i++) {
        g_off[i] = run;
        int dg = g_deg[i];
        run += dg;
        g_dinv[i] = rsqrtf((float)(dg + 1));  // +1: self-loop
    }
    if (start < N_NODES && end == N_NODES) g_off[N_NODES] = run;
}

// ---------------- pass 2: place into CSR with norm ---------------------------
__global__ void k_place() {
    int e = blockIdx.x * blockDim.x + threadIdx.x;
    if (e >= N_EDGES) return;
    int s = g_src[e];
    int d = g_dst[e];
    float nz = g_dinv[s] * g_dinv[d];
    int pos = g_off[d] + atomicAdd(&g_cur[d], 1);
    g_csrc[pos] = s;
    g_cnorm[pos] = nz;
}

// ---------------- GEMM: [32 rows] x [64 -> OUT], fp16 output -----------------
// FROM_X: input from param x; else from g_agg (fp32) with ReLU fused.
template <int OUT, bool FROM_X>
__global__ void k_gemm(const float* __restrict__ x, const float* __restrict__ W) {
    constexpr int QUADS = OUT / 4;
    constexpr int RPT = (32 * QUADS) / 256;  // 2 for OUT=64, 1 for OUT=32
    __shared__ float Ws[64 * OUT];
    __shared__ float xs[32][65];  // pad kills stride-64 bank conflicts

    const int tid = threadIdx.x;
    const int row0 = blockIdx.x * 32;  // N_NODES % 32 == 0

    for (int i = tid; i < 64 * OUT; i += 256) Ws[i] = W[i];

    for (int i = tid; i < 32 * 16; i += 256) {
        int r = i >> 4, c4 = i & 15;
        float4 v;
        if (FROM_X) {
            v = *(const float4*)&x[(size_t)(row0 + r) * 64 + c4 * 4];
        } else {
            v = *(const float4*)&g_agg[(size_t)(row0 + r) * 64 + c4 * 4];
            v.x = fmaxf(v.x, 0.f); v.y = fmaxf(v.y, 0.f);
            v.z = fmaxf(v.z, 0.f); v.w = fmaxf(v.w, 0.f);
        }
        xs[r][c4 * 4 + 0] = v.x; xs[r][c4 * 4 + 1] = v.y;
        xs[r][c4 * 4 + 2] = v.z; xs[r][c4 * 4 + 3] = v.w;
    }
    __syncthreads();

    const int colq = tid % QUADS;
    const int rg = tid / QUADS;

    float acc[RPT][4];
#pragma unroll
    for (int r = 0; r < RPT; r++) { acc[r][0] = acc[r][1] = acc[r][2] = acc[r][3] = 0.f; }

#pragma unroll
    for (int k = 0; k < 64; k++) {
        float4 w = *(const float4*)&Ws[k * OUT + colq * 4];
#pragma unroll
        for (int r = 0; r < RPT; r++) {
            float xv = xs[rg * RPT + r][k];
            acc[r][0] = fmaf(xv, w.x, acc[r][0]);
            acc[r][1] = fmaf(xv, w.y, acc[r][1]);
            acc[r][2] = fmaf(xv, w.z, acc[r][2]);
            acc[r][3] = fmaf(xv, w.w, acc[r][3]);
        }
    }

#pragma unroll
    for (int r = 0; r < RPT; r++) {
        int row = row0 + rg * RPT + r;
        __half2 h0 = __floats2half2_rn(acc[r][0], acc[r][1]);
        __half2 h1 = __floats2half2_rn(acc[r][2], acc[r][3]);
        // 8-byte store of 4 halves
        *(uint2*)&g_hh[(size_t)row * OUT + colq * 4] =
            make_uint2(*(unsigned*)&h0, *(unsigned*)&h1);
    }
}

// ---------------- CSR aggregation: full warp per node, fp16 gather -----------
// out[node] = dinv^2*h[node] + b + sum_e norm_e * h[src_e]   (fp32 accumulate)
// OUT=64: lane owns cols {2L, 2L+1} as one half2 -> one LDG.32 per edge.
// OUT=32: lane owns col L as one half -> one LDG.U16 per edge.
template <int OUT, bool TO_OUT>
__global__ void k_agg(const float* __restrict__ b, float* __restrict__ out) {
    const int warp = (blockIdx.x * blockDim.x + threadIdx.x) >> 5;
    const int lane = threadIdx.x & 31;
    if (warp >= N_NODES) return;
    const int node = warp;

    const int beg = g_off[node];
    const int end = g_off[node + 1];

    if (OUT == 64) {
        const __half2* h2 = (const __half2*)g_hh;
        float2 acc;
        {
            float di = g_dinv[node];
            float sc = di * di;
            float2 hv = __half22float2(h2[(size_t)node * 32 + lane]);
            float2 bq = ((const float2*)b)[lane];
            acc.x = fmaf(sc, hv.x, bq.x);
            acc.y = fmaf(sc, hv.y, bq.y);
        }
        for (int p = beg; p < end; p++) {
            int s = g_csrc[p];           // warp-uniform
            float nz = g_cnorm[p];       // warp-uniform
            float2 hv = __half22float2(h2[(size_t)s * 32 + lane]);
            acc.x = fmaf(nz, hv.x, acc.x);
            acc.y = fmaf(nz, hv.y, acc.y);
        }
        if (TO_OUT) ((float2*)out)[(size_t)node * 32 + lane] = acc;
        else        ((float2*)g_agg)[(size_t)node * 32 + lane] = acc;
    } else {
        float acc;
        {
            float di = g_dinv[node];
            float sc = di * di;
            acc = fmaf(sc, __half2float(g_hh[(size_t)node * 32 + lane]), b[lane]);
        }
        for (int p = beg; p < end; p++) {
            int s = g_csrc[p];
            float nz = g_cnorm[p];
            acc = fmaf(nz, __half2float(g_hh[(size_t)s * 32 + lane]), acc);
        }
        if (TO_OUT) out[(size_t)node * 32 + lane] = acc;
        else        g_agg[(size_t)node * 32 + lane] = acc;
    }
}

// ---------------- launch: kernel launches ONLY --------------------------------
extern "C" void kernel_launch(void* const* d_in, const int* in_sizes, int n_in,
                              void* d_out, int out_size) {
    const float* x  = (const float*)d_in[0];
    const int* ei   = (const int*)d_in[1];   // int32 (JAX x64 off); int64 auto-detected
    const float* W1 = (const float*)d_in[2];
    const float* b1 = (const float*)d_in[3];
    const float* W2 = (const float*)d_in[4];
    const float* b2 = (const float*)d_in[5];
    const float* W3 = (const float*)d_in[6];
    const float* b3 = (const float*)d_in[7];
    float* out      = (float*)d_out;

    const int T = 256;
    const int gN = (N_NODES + T - 1) / T;
    const int gE = (N_EDGES + T - 1) / T;
    const int gW = (N_NODES * 32 + T - 1) / T;  // one warp per node

    // CSR build (4 launches)
    k_zero<<<gN, T>>>(ei);
    k_pre<<<gE, T>>>(ei);
    k_scan<<<1, 1024>>>();
    k_place<<<gE, T>>>();

    // Layer 1
    k_gemm<64, true><<<N_NODES / 32, T>>>(x, W1);
    k_agg<64, false><<<gW, T>>>(b1, nullptr);

    // Layer 2
    k_gemm<64, false><<<N_NODES / 32, T>>>(nullptr, W2);
    k_agg<64, false><<<gW, T>>>(b2, nullptr);

    // Layer 3 (OUT=32) -> harness output
    k_gemm<32, false><<<N_NODES / 32, T>>>(nullptr, W3);
    k_agg<32, true><<<gW, T>>>(b3, out);
}

// round 17
// speedup vs baseline: 1.1245x; 1.1176x over previous
#include <cuda_runtime.h>
#include <cuda_fp16.h>
#include <mma.h>

using namespace nvcuda;

#define N_NODES 100000
#define N_EDGES 1600000
#define GEMM_BLOCKS ((N_NODES + 63) / 64)   // 1563

// ---------------- scratch: __device__ globals --------------------------------
__device__ __align__(16) __half g_xh[N_NODES * 64];   // x in fp16 (gemm1 input)
__device__ __align__(16) __half g_hh[N_NODES * 64];   // GEMM out fp16 (gather src)
__device__ __align__(16) __half g_ah[N_NODES * 64];   // agg out fp16+relu (gemm input)
__device__ float g_dinv[N_NODES];
__device__ int   g_deg[N_NODES];
__device__ int   g_cur[N_NODES];
__device__ int   g_off[N_NODES + 1];
__device__ int   g_csrc[N_EDGES];
__device__ float g_cnorm[N_EDGES];
__device__ int   g_is64;

// ---------------- init: zero counters, convert x -> fp16, dtype detect -------
__global__ void k_init(const int* __restrict__ ei, const float* __restrict__ x) {
    int i = blockIdx.x * blockDim.x + threadIdx.x;
    if (i < N_NODES) { g_deg[i] = 0; g_cur[i] = 0; }
    if (i < N_NODES * 32) {                    // 3.2M half2 elements
        float2 v = ((const float2*)x)[i];
        ((__half2*)g_xh)[i] = __floats2half2_rn(v.x, v.y);
    }
    if (blockIdx.x == 0) {
        __shared__ int nonzero;
        if (threadIdx.x == 0) nonzero = 0;
        __syncthreads();
        if (ei[2 * threadIdx.x + 1] != 0) atomicAdd(&nonzero, 1);
        __syncthreads();
        if (threadIdx.x == 0) g_is64 = (nonzero == 0) ? 1 : 0;
    }
}

__device__ __forceinline__ void decode_edge(const int* __restrict__ ei, int e,
                                            int& s, int& d) {
    if (g_is64) { s = ei[2 * e]; d = ei[2 * (N_EDGES + e)]; }
    else        { s = ei[e];     d = ei[N_EDGES + e]; }
    if ((unsigned)s >= N_NODES) s = 0;
    if ((unsigned)d >= N_NODES) d = 0;
}

// ---------------- pass 1: degree count ---------------------------------------
__global__ void k_pre(const int* __restrict__ ei) {
    int e = blockIdx.x * blockDim.x + threadIdx.x;
    if (e >= N_EDGES) return;
    int s, d;
    decode_edge(ei, e, s, d);
    atomicAdd(&g_deg[d], 1);
}

// ---------------- scan body (256 threads): offsets + dinv --------------------
__device__ void scan_body() {
    __shared__ int partial[256];
    const int tid = threadIdx.x;
    const int chunk = (N_NODES + 255) / 256;  // 391
    const int start = tid * chunk;
    const int end = min(start + chunk, N_NODES);

    int s = 0;
    for (int i = start; i < end; i++) s += g_deg[i];
    partial[tid] = s;
    __syncthreads();
    for (int off = 1; off < 256; off <<= 1) {
        int v = (tid >= off) ? partial[tid - off] : 0;
        __syncthreads();
        partial[tid] += v;
        __syncthreads();
    }
    int run = (tid > 0) ? partial[tid - 1] : 0;
    for (int i = start; i < end; i++) {
        g_off[i] = run;
        int dg = g_deg[i];
        run += dg;
        g_dinv[i] = rsqrtf((float)(dg + 1));  // +1: self-loop
    }
    if (start < N_NODES && end == N_NODES) g_off[N_NODES] = run;
}

// ---------------- pass 2: re-decode, norm, place into CSR --------------------
__global__ void k_place(const int* __restrict__ ei) {
    int e = blockIdx.x * blockDim.x + threadIdx.x;
    if (e >= N_EDGES) return;
    int s, d;
    decode_edge(ei, e, s, d);
    float nz = g_dinv[s] * g_dinv[d];
    int pos = g_off[d] + atomicAdd(&g_cur[d], 1);
    g_csrc[pos] = s;
    g_cnorm[pos] = nz;
}

// ---------------- tensor-core GEMM: 64 rows/block, fp16 x fp16 -> fp32 -------
// in: fp16 [N,64]; Wf: fp32 [64,OUT] (converted to fp16 in smem).
// Writes g_hh fp16 [N,OUT]. WITH_SCAN: one extra block runs scan_body().
template <int OUT, bool WITH_SCAN>
__global__ void k_gemm_tc(const __half* __restrict__ in, const float* __restrict__ Wf) {
    if (WITH_SCAN && blockIdx.x == GEMM_BLOCKS) { scan_body(); return; }

    __shared__ __half xs[64 * 64];    // 8 KB, row-major ld=64
    __shared__ __half ws[64 * OUT];   // <=8 KB, row-major ld=OUT
    __shared__ float  os[64 * OUT];   // <=16 KB, row-major ld=OUT

    const int tid = threadIdx.x;      // 256 threads = 8 warps (4 compute)
    const int warp = tid >> 5;
    const int row0 = blockIdx.x * 64;

    // load 64x64 fp16 tile (8 int4 per row); zero-pad rows >= N_NODES
    {
        const int4* src = (const int4*)in;
        int4* dst = (int4*)xs;
        for (int i = tid; i < 64 * 8; i += 256) {
            int r = i >> 3;
            int4 v = make_int4(0, 0, 0, 0);
            if (row0 + r < N_NODES) v = src[(size_t)(row0 + r) * 8 + (i & 7)];
            dst[i] = v;
        }
    }
    // W fp32 -> fp16
    for (int i = tid; i < 64 * OUT; i += 256) ws[i] = __float2half(Wf[i]);
    __syncthreads();

    // warps 0..3 compute 16 rows x OUT cols each
    if (warp < 4) {
        wmma::fragment<wmma::accumulator, 16, 16, 16, float> acc[OUT / 16];
#pragma unroll
        for (int c = 0; c < OUT / 16; c++) wmma::fill_fragment(acc[c], 0.0f);
#pragma unroll
        for (int k = 0; k < 4; k++) {
            wmma::fragment<wmma::matrix_a, 16, 16, 16, __half, wmma::row_major> af;
            wmma::load_matrix_sync(af, xs + (warp * 16) * 64 + k * 16, 64);
#pragma unroll
            for (int c = 0; c < OUT / 16; c++) {
                wmma::fragment<wmma::matrix_b, 16, 16, 16, __half, wmma::row_major> bf;
                wmma::load_matrix_sync(bf, ws + (k * 16) * OUT + c * 16, OUT);
                wmma::mma_sync(acc[c], af, bf, acc[c]);
            }
        }
#pragma unroll
        for (int c = 0; c < OUT / 16; c++)
            wmma::store_matrix_sync(os + (warp * 16) * OUT + c * 16, acc[c], OUT,
                                    wmma::mem_row_major);
    }
    __syncthreads();

    // fp32 smem -> fp16 global
    {
        __half2* dst = (__half2*)g_hh;
        for (int i = tid; i < 64 * OUT / 2; i += 256) {
            int r = i / (OUT / 2);
            int c2 = i % (OUT / 2);
            if (row0 + r < N_NODES)
                dst[(size_t)(row0 + r) * (OUT / 2) + c2] =
                    __floats2half2_rn(os[r * OUT + c2 * 2], os[r * OUT + c2 * 2 + 1]);
        }
    }
}

// ---------------- CSR aggregation: full warp per node, fp16 gather -----------
// acc = dinv^2*h[node] + b + sum_e norm_e * h[src_e]    (fp32 accumulate)
// FINAL: write fp32 to out. else: write relu(acc) as fp16 to g_ah.
template <int OUT, bool FINAL>
__global__ void k_agg(const float* __restrict__ b, float* __restrict__ out) {
    const int warp = (blockIdx.x * blockDim.x + threadIdx.x) >> 5;
    const int lane = threadIdx.x & 31;
    if (warp >= N_NODES) return;
    const int node = warp;

    const int beg = g_off[node];
    const int end = g_off[node + 1];

    if (OUT == 64) {
        const __half2* h2 = (const __half2*)g_hh;
        float2 acc;
        {
            float di = g_dinv[node];
            float sc = di * di;
            float2 hv = __half22float2(h2[(size_t)node * 32 + lane]);
            float2 bq = ((const float2*)b)[lane];
            acc.x = fmaf(sc, hv.x, bq.x);
            acc.y = fmaf(sc, hv.y, bq.y);
        }
        for (int p = beg; p < end; p++) {
            int s = g_csrc[p];            // warp-uniform
            float nz = g_cnorm[p];        // warp-uniform
            float2 hv = __half22float2(h2[(size_t)s * 32 + lane]);
            acc.x = fmaf(nz, hv.x, acc.x);
            acc.y = fmaf(nz, hv.y, acc.y);
        }
        if (FINAL) {
            ((float2*)out)[(size_t)node * 32 + lane] = acc;
        } else {
            ((__half2*)g_ah)[(size_t)node * 32 + lane] =
                __floats2half2_rn(fmaxf(acc.x, 0.f), fmaxf(acc.y, 0.f));
        }
    } else {  // OUT == 32
        float acc;
        {
            float di = g_dinv[node];
            float sc = di * di;
            acc = fmaf(sc, __half2float(g_hh[(size_t)node * 32 + lane]), b[lane]);
        }
        for (int p = beg; p < end; p++) {
            int s = g_csrc[p];
            float nz = g_cnorm[p];
            acc = fmaf(nz, __half2float(g_hh[(size_t)s * 32 + lane]), acc);
        }
        if (FINAL) out[(size_t)node * 32 + lane] = acc;
        else g_ah[(size_t)node * 32 + lane] = __float2half(fmaxf(acc, 0.f));
    }
}

// ---------------- launch: kernel launches ONLY --------------------------------
extern "C" void kernel_launch(void* const* d_in, const int* in_sizes, int n_in,
                              void* d_out, int out_size) {
    const float* x  = (const float*)d_in[0];
    const int* ei   = (const int*)d_in[1];   // int32 (JAX x64 off); int64 auto-detected
    const float* W1 = (const float*)d_in[2];
    const float* b1 = (const float*)d_in[3];
    const float* W2 = (const float*)d_in[4];
    const float* b2 = (const float*)d_in[5];
    const float* W3 = (const float*)d_in[6];
    const float* b3 = (const float*)d_in[7];
    float* out      = (float*)d_out;

    const int T = 256;
    const int gE = (N_EDGES + T - 1) / T;           // 6250
    const int gI = (N_NODES * 32 + T - 1) / T;      // 12500 (x convert)
    const int gW = (N_NODES * 32 + T - 1) / T;      // one warp per node

    __half* xh = nullptr;  __half* ah = nullptr;
    cudaGetSymbolAddress((void**)&xh, g_xh);
    cudaGetSymbolAddress((void**)&ah, g_ah);

    // build: init -> count -> [gemm1 || scan] -> place
    k_init<<<gI, T>>>(ei, x);
    k_pre<<<gE, T>>>(ei);
    k_gemm_tc<64, true><<<GEMM_BLOCKS + 1, T>>>(xh, W1);   // scan rides as last block
    k_place<<<gE, T>>>(ei);

    // Layer 1 agg -> fp16+relu
    k_agg<64, false><<<gW, T>>>(b1, nullptr);

    // Layer 2
    k_gemm_tc<64, false><<<GEMM_BLOCKS, T>>>(ah, W2);
    k_agg<64, false><<<gW, T>>>(b2, nullptr);

    // Layer 3 (OUT=32) -> harness output (fp32)
    k_gemm_tc<32, false><<<GEMM_BLOCKS, T>>>(ah, W3);
    k_agg<32, true><<<gW, T>>>(b3, out);
}